// round 4
// baseline (speedup 1.0000x reference)
#include <cuda_runtime.h>
#include <cstddef>

#define NN   50000
#define NE   400000
#define NLE  3200000
#define F    32
#define SCAN_B 1024
#define SBG   ((NN + SCAN_B - 1) / SCAN_B)   // 49
#define SBL   ((NE + SCAN_B - 1) / SCAN_B)   // 391

typedef unsigned long long u64;

// ---------------- scratch (device globals, zero-initialized at load) ----------------
__device__ float d_zg0[NN * F];
__device__ float d_zg1[NN * F];
__device__ float d_zg2[NN * F];
__device__ float d_zgt[NN * F];
__device__ float d_pmy[NN * F];
__device__ float d_zl0[NE * F];
__device__ float d_zl1[NE * F];
__device__ float d_zl2[NE * F];
__device__ float d_zlt[NE * F];
__device__ float d_stats[128];          // zeroed by hist block 0 each replay

__device__ int d_cnt[NN + NE];          // zeroed by scan_add_cur each replay
__device__ int d_incl[NN + NE];
__device__ int d_cur[NN + NE];
__device__ int d_off[(NN + 1) + (NE + 1)];
__device__ int d_csr_src_g[NE];
__device__ int d_csr_eid_g[NE];
__device__ int d_csr_lg[NLE];
__device__ int d_bsum[1024];            // g at [0,512), lg at [512,1024)

// ---------------- f32x2 helpers ----------------
__device__ __forceinline__ u64 pack2(float a, float b) {
    u64 r; asm("mov.b64 %0, {%1, %2};" : "=l"(r) : "f"(a), "f"(b)); return r;
}
__device__ __forceinline__ void unpack2(u64 v, float& a, float& b) {
    asm("mov.b64 {%0, %1}, %2;" : "=f"(a), "=f"(b) : "l"(v));
}
__device__ __forceinline__ u64 fma2(u64 a, u64 b, u64 c) {
    u64 d; asm("fma.rn.f32x2 %0, %1, %2, %3;" : "=l"(d) : "l"(a), "l"(b), "l"(c)); return d;
}

// ================= CSR build =================
__global__ void hist_both_kernel(const int* __restrict__ g_dst, const int* __restrict__ lg_dst,
                                 int* __restrict__ cnt, float* __restrict__ st) {
    if (blockIdx.x == 0 && threadIdx.x < 128) st[threadIdx.x] = 0.f;  // stats reset for this replay
    int t = blockIdx.x * blockDim.x + threadIdx.x;
    if (t < NE) {
        atomicAdd(&cnt[__ldg(g_dst + t)], 1);
    } else if (t < NE + NLE) {
        atomicAdd(&cnt[NN + __ldg(lg_dst + (t - NE))], 1);
    }
}

// warp-shuffle inclusive scan per 1024-block; writes incl + per-block sum
__global__ void scan_block_kernel(const int* __restrict__ cnt, int* __restrict__ incl,
                                  int* __restrict__ bsum) {
    int b = blockIdx.x;
    const int* c; int* in; int n; int* bs; int rel;
    if (b < SBG) { c = cnt;      in = incl;      n = NN; bs = bsum;       rel = b; }
    else         { c = cnt + NN; in = incl + NN; n = NE; bs = bsum + 512; rel = b - SBG; }
    int tid = threadIdx.x;
    int lane = tid & 31, wid = tid >> 5;
    int i = rel * SCAN_B + tid;
    int v = (i < n) ? c[i] : 0;
    int sv = v;
#pragma unroll
    for (int o = 1; o < 32; o <<= 1) {
        int t2 = __shfl_up_sync(~0u, sv, o);
        if (lane >= o) sv += t2;
    }
    __shared__ int ws[32];
    if (lane == 31) ws[wid] = sv;
    __syncthreads();
    if (wid == 0) {
        int w = ws[lane];
#pragma unroll
        for (int o = 1; o < 32; o <<= 1) {
            int t2 = __shfl_up_sync(~0u, w, o);
            if (lane >= o) w += t2;
        }
        ws[lane] = w;
    }
    __syncthreads();
    int inc = sv + (wid ? ws[wid - 1] : 0);
    if (i < n) in[i] = inc;
    if (tid == SCAN_B - 1) bs[rel] = inc;
}

// per-block local prefix over bsums; writes off & cur; zeroes cnt for next replay
__global__ void scan_add_cur_kernel(const int* __restrict__ incl, int* __restrict__ cnt,
                                    const int* __restrict__ bsum,
                                    int* __restrict__ off, int* __restrict__ cur) {
    int b = blockIdx.x;
    const int* in; int* c; int n; const int* bs; int rel; int* o_; int* cu;
    if (b < SBG) { in = incl;      c = cnt;      n = NN; bs = bsum;       rel = b;       o_ = off;          cu = cur; }
    else         { in = incl + NN; c = cnt + NN; n = NE; bs = bsum + 512; rel = b - SBG; o_ = off + NN + 1; cu = cur + NN; }
    __shared__ int red[SCAN_B];
    int t = threadIdx.x;
    red[t] = (t < rel) ? bs[t] : 0;
    __syncthreads();
#pragma unroll
    for (int o = SCAN_B / 2; o > 0; o >>= 1) {
        if (t < o) red[t] += red[t + o];
        __syncthreads();
    }
    int prefix = red[0];
    int i = rel * SCAN_B + t;
    if (i < n) {
        int inc = in[i] + prefix;
        o_[i + 1] = inc;
        cu[i] = inc - c[i];
        c[i] = 0;                      // self-clean for next replay
        if (i == 0) o_[0] = 0;
    }
}

__global__ void fill_both_kernel(const int* __restrict__ g_src, const int* __restrict__ g_dst,
                                 const int* __restrict__ lg_src, const int* __restrict__ lg_dst,
                                 int* __restrict__ cur,
                                 int* __restrict__ csr_src_g, int* __restrict__ csr_eid_g,
                                 int* __restrict__ csr_lg) {
    int t = blockIdx.x * blockDim.x + threadIdx.x;
    if (t < NE) {
        int p = atomicAdd(&cur[__ldg(g_dst + t)], 1);
        csr_src_g[p] = __ldg(g_src + t);
        csr_eid_g[p] = t;
    } else if (t < NE + NLE) {
        int e = t - NE;
        int p = atomicAdd(&cur[NN + __ldg(lg_dst + e)], 1);
        csr_lg[p] = __ldg(lg_src + e);
    }
}

// ================= pull SpMM =================
__device__ __forceinline__ void pull_row(const float* __restrict__ z, const int* __restrict__ off,
                                         const int* __restrict__ idx, float* __restrict__ out,
                                         int r, int lane) {
    int b = __ldg(off + r), e = __ldg(off + r + 1);
    float4 acc = make_float4(0.f, 0.f, 0.f, 0.f);
    int i = b;
    for (; i + 3 < e; i += 4) {
        int s0 = __ldg(idx + i), s1 = __ldg(idx + i + 1);
        int s2 = __ldg(idx + i + 2), s3 = __ldg(idx + i + 3);
        float4 v0 = *((const float4*)(z + (size_t)s0 * F) + lane);
        float4 v1 = *((const float4*)(z + (size_t)s1 * F) + lane);
        float4 v2 = *((const float4*)(z + (size_t)s2 * F) + lane);
        float4 v3 = *((const float4*)(z + (size_t)s3 * F) + lane);
        acc.x += (v0.x + v1.x) + (v2.x + v3.x);
        acc.y += (v0.y + v1.y) + (v2.y + v3.y);
        acc.z += (v0.z + v1.z) + (v2.z + v3.z);
        acc.w += (v0.w + v1.w) + (v2.w + v3.w);
    }
    for (; i < e; i++) {
        int s0 = __ldg(idx + i);
        float4 v0 = *((const float4*)(z + (size_t)s0 * F) + lane);
        acc.x += v0.x; acc.y += v0.y; acc.z += v0.z; acc.w += v0.w;
    }
    *((float4*)(out + (size_t)r * F) + lane) = acc;
}

__global__ void hops_kernel(
    const float* __restrict__ z1, const int* __restrict__ off1, const int* __restrict__ idx1,
    float* __restrict__ o1, int n1,
    const float* __restrict__ z2, const int* __restrict__ off2, const int* __restrict__ idx2,
    float* __restrict__ o2, int n2,
    const float* __restrict__ z3, const int* __restrict__ off3, const int* __restrict__ idx3,
    float* __restrict__ o3, int n3)
{
    long long t = (long long)blockIdx.x * blockDim.x + threadIdx.x;
    int r = (int)(t >> 3);
    int lane = (int)(t & 7);
    if (r < n1) {
        pull_row(z1, off1, idx1, o1, r, lane);
    } else if (r < n1 + n2) {
        pull_row(z2, off2, idx2, o2, r - n1, lane);
    } else if (r < n1 + n2 + n3) {
        pull_row(z3, off3, idx3, o3, r - n1 - n2, lane);
    }
}

// ================= fused assemble + BN stats =================
__device__ __forceinline__ void mv_acc2(u64 acc[16], const float* __restrict__ vec,
                                        float scale, const u64 (&W)[F][16]) {
    const float4* vp = (const float4*)vec;
#pragma unroll 1
    for (int k4 = 0; k4 < 8; k4++) {
        float4 v = vp[k4];
        float c0 = v.x * scale, c1 = v.y * scale, c2 = v.z * scale, c3 = v.w * scale;
        u64 a0 = pack2(c0, c0), a1 = pack2(c1, c1), a2 = pack2(c2, c2), a3 = pack2(c3, c3);
#pragma unroll
        for (int j = 0; j < 16; j++) acc[j] = fma2(a0, W[k4 * 4 + 0][j], acc[j]);
#pragma unroll
        for (int j = 0; j < 16; j++) acc[j] = fma2(a1, W[k4 * 4 + 1][j], acc[j]);
#pragma unroll
        for (int j = 0; j < 16; j++) acc[j] = fma2(a2, W[k4 * 4 + 2][j], acc[j]);
#pragma unroll
        for (int j = 0; j < 16; j++) acc[j] = fma2(a3, W[k4 * 4 + 3][j], acc[j]);
    }
}

__global__ void assemble_both_kernel(
    const float* __restrict__ xb, const float* __restrict__ xdeg, const float* __restrict__ xextra,
    const float* __restrict__ xz0, const float* __restrict__ xz1, const float* __restrict__ xz2,
    const float* __restrict__ xWm, const float* __restrict__ xbm,
    const float* __restrict__ xWl, const float* __restrict__ xbl,
    float* __restrict__ xout, int nx, int bx,
    const float* __restrict__ yb, const float* __restrict__ ydeg, const float* __restrict__ yextra,
    const int* __restrict__ gatherIdx,
    const float* __restrict__ yz0, const float* __restrict__ yz1, const float* __restrict__ yz2,
    const float* __restrict__ yWm, const float* __restrict__ ybm,
    const float* __restrict__ yWl, const float* __restrict__ ybl,
    float* __restrict__ yout, int ny,
    float* __restrict__ st)
{
    bool isX = (int)blockIdx.x < bx;
    const float* base  = isX ? xb : yb;
    const float* deg   = isX ? xdeg : ydeg;
    const float* extra = isX ? xextra : yextra;
    const float* z0 = isX ? xz0 : yz0;
    const float* z1 = isX ? xz1 : yz1;
    const float* z2 = isX ? xz2 : yz2;
    const float* Wmain = isX ? xWm : yWm;
    const float* bmain = isX ? xbm : ybm;
    const float* Wlist = isX ? xWl : yWl;
    const float* blist = isX ? xbl : ybl;
    float* out = isX ? xout : yout;
    int n = isX ? nx : ny;
    int rblock = isX ? (int)blockIdx.x : (int)blockIdx.x - bx;
    float* st0 = st + (isX ? 0 : 64);

    __shared__ u64 sW[6][F][16];
    __shared__ u64 sb[16];
    __shared__ float sSum[8][F];
    __shared__ float sSq[8][F];
    for (int i = threadIdx.x; i < 6 * F * 16; i += blockDim.x) {
        int m = i >> 9;
        int rem = i & 511;
        int k = rem >> 4;
        int j2 = rem & 15;
        const float* W = (m < 3) ? (Wmain + m * 1024) : (Wlist + (m - 3) * 1024);
        sW[m][k][j2] = pack2(W[(2 * j2) * 32 + k], W[(2 * j2 + 1) * 32 + k]);
    }
    if (threadIdx.x < 16) {
        int j2 = threadIdx.x;
        float b0 = 0.f, b1 = 0.f;
#pragma unroll
        for (int m = 0; m < 3; m++) {
            b0 += bmain[m * 32 + 2 * j2] + blist[m * 32 + 2 * j2];
            b1 += bmain[m * 32 + 2 * j2 + 1] + blist[m * 32 + 2 * j2 + 1];
        }
        sb[j2] = pack2(b0, b1);
    }
    __syncthreads();

    int r = rblock * blockDim.x + threadIdx.x;
    bool live = (r < n);
    float vals[F];

    if (live) {
        u64 acc[16];
#pragma unroll
        for (int j = 0; j < 16; j++) acc[j] = sb[j];
        size_t r32 = (size_t)r * F;
        float dg = deg[r];
        mv_acc2(acc, base + r32, 1.f, sW[0]);
        mv_acc2(acc, base + r32, dg,  sW[1]);
        const float* ex = isX ? (extra + r32) : (extra + (size_t)__ldg(gatherIdx + r) * F);
        mv_acc2(acc, ex,        1.f, sW[2]);
        mv_acc2(acc, z0 + r32,  1.f, sW[3]);
        mv_acc2(acc, z1 + r32,  1.f, sW[4]);
        mv_acc2(acc, z2 + r32,  1.f, sW[5]);
#pragma unroll
        for (int j = 0; j < 16; j++) unpack2(acc[j], vals[2 * j], vals[2 * j + 1]);
#pragma unroll
        for (int j = F / 2; j < F; j++) vals[j] = fmaxf(vals[j], 0.f);
        float4* op = (float4*)(out + r32);
#pragma unroll
        for (int j = 0; j < 8; j++)
            op[j] = make_float4(vals[4 * j], vals[4 * j + 1], vals[4 * j + 2], vals[4 * j + 3]);
    } else {
#pragma unroll
        for (int j = 0; j < F; j++) vals[j] = 0.f;
    }

    // ---- in-kernel BN stats: warp butterfly per column, smem combine, global RED ----
    int lane = threadIdx.x & 31;
    int wid = threadIdx.x >> 5;
#pragma unroll
    for (int j = 0; j < F; j++) {
        float a = vals[j];
        float q = a * a;
#pragma unroll
        for (int o = 16; o > 0; o >>= 1) {
            a += __shfl_xor_sync(~0u, a, o);
            q += __shfl_xor_sync(~0u, q, o);
        }
        if (lane == 0) { sSum[wid][j] = a; sSq[wid][j] = q; }
    }
    __syncthreads();
    if (threadIdx.x < F) {
        float a = 0.f;
#pragma unroll
        for (int w = 0; w < 8; w++) a += sSum[w][threadIdx.x];
        atomicAdd(&st0[threadIdx.x], a);
    } else if (threadIdx.x < 2 * F) {
        int j = threadIdx.x - F;
        float q = 0.f;
#pragma unroll
        for (int w = 0; w < 8; w++) q += sSq[w][j];
        atomicAdd(&st0[F + j], q);
    }
}

// ================= BN normalize =================
__global__ void normalize_both_kernel(float* __restrict__ vx, float* __restrict__ vy,
                                      int gx, const float* __restrict__ st,
                                      const float* __restrict__ sx, const float* __restrict__ bxx,
                                      const float* __restrict__ sy, const float* __restrict__ byy) {
    bool isX = (int)blockIdx.x < gx;
    float* v = isX ? vx : vy;
    long long nRows = isX ? NN : NE;
    const float* s0 = st + (isX ? 0 : 64);
    const float* scale = isX ? sx : sy;
    const float* bias  = isX ? bxx : byy;
    int nb = isX ? gx : (gridDim.x - gx);
    int rb = isX ? (int)blockIdx.x : (int)blockIdx.x - gx;

    __shared__ float mulc[F], addc[F];
    if (threadIdx.x < F) {
        float m = s0[threadIdx.x] / (float)nRows;
        float var = s0[F + threadIdx.x] / (float)nRows - m * m;
        float g = rsqrtf(var + 1e-5f) * scale[threadIdx.x];
        mulc[threadIdx.x] = g;
        addc[threadIdx.x] = bias[threadIdx.x] - m * g;
    }
    __syncthreads();
    int col = threadIdx.x & 31;
    int w = threadIdx.x >> 5;
    int warpsPerBlock = blockDim.x >> 5;
    for (long long r = (long long)rb * warpsPerBlock + w; r < nRows;
         r += (long long)nb * warpsPerBlock) {
        v[r * F + col] = fmaf(v[r * F + col], mulc[col], addc[col]);
    }
}

// ================= launcher =================
extern "C" void kernel_launch(void* const* d_in, const int* in_sizes, int n_in,
                              void* d_out, int out_size) {
    const float* x            = (const float*)d_in[0];
    const float* y            = (const float*)d_in[1];
    const float* deg_g        = (const float*)d_in[2];
    const float* deg_lg       = (const float*)d_in[3];
    const float* theta_main_w = (const float*)d_in[4];
    const float* theta_main_b = (const float*)d_in[5];
    const float* theta_list_w = (const float*)d_in[6];
    const float* theta_list_b = (const float*)d_in[7];
    const float* gamma_main_w = (const float*)d_in[8];
    const float* gamma_main_b = (const float*)d_in[9];
    const float* gamma_list_w = (const float*)d_in[10];
    const float* gamma_list_b = (const float*)d_in[11];
    const float* bn_x_scale   = (const float*)d_in[12];
    const float* bn_x_bias    = (const float*)d_in[13];
    const float* bn_y_scale   = (const float*)d_in[14];
    const float* bn_y_bias    = (const float*)d_in[15];
    const int*   g_src        = (const int*)d_in[16];
    const int*   g_dst        = (const int*)d_in[17];
    const int*   lg_src       = (const int*)d_in[18];
    const int*   lg_dst       = (const int*)d_in[19];
    const int*   pm_pd        = (const int*)d_in[20];

    float* out_x = (float*)d_out;
    float* out_y = (float*)d_out + (size_t)NN * F;

    float *zg0, *zg1, *zg2, *zgt, *pmy, *zl0, *zl1, *zl2, *zlt, *st;
    int *cnt, *incl, *cur, *off, *csr_src_g, *csr_eid_g, *csr_lg, *bsum;
    cudaGetSymbolAddress((void**)&zg0, d_zg0);
    cudaGetSymbolAddress((void**)&zg1, d_zg1);
    cudaGetSymbolAddress((void**)&zg2, d_zg2);
    cudaGetSymbolAddress((void**)&zgt, d_zgt);
    cudaGetSymbolAddress((void**)&pmy, d_pmy);
    cudaGetSymbolAddress((void**)&zl0, d_zl0);
    cudaGetSymbolAddress((void**)&zl1, d_zl1);
    cudaGetSymbolAddress((void**)&zl2, d_zl2);
    cudaGetSymbolAddress((void**)&zlt, d_zlt);
    cudaGetSymbolAddress((void**)&st,  d_stats);
    cudaGetSymbolAddress((void**)&cnt, d_cnt);
    cudaGetSymbolAddress((void**)&incl, d_incl);
    cudaGetSymbolAddress((void**)&cur, d_cur);
    cudaGetSymbolAddress((void**)&off, d_off);
    cudaGetSymbolAddress((void**)&csr_src_g, d_csr_src_g);
    cudaGetSymbolAddress((void**)&csr_eid_g, d_csr_eid_g);
    cudaGetSymbolAddress((void**)&csr_lg, d_csr_lg);
    cudaGetSymbolAddress((void**)&bsum, d_bsum);

    int* off_g  = off;
    int* off_lg = off + NN + 1;

    const int TB = 256;
    int eBlocks = (NE + NLE + TB - 1) / TB;

    // ===== CSR build (4 launches, no memsets) =====
    hist_both_kernel<<<eBlocks, TB>>>(g_dst, lg_dst, cnt, st);
    scan_block_kernel<<<SBG + SBL, SCAN_B>>>(cnt, incl, bsum);
    scan_add_cur_kernel<<<SBG + SBL, SCAN_B>>>(incl, cnt, bsum, off, cur);
    fill_both_kernel<<<eBlocks, TB>>>(g_src, g_dst, lg_src, lg_dst, cur,
                                      csr_src_g, csr_eid_g, csr_lg);

    // ===== hops =====
    long long rows1 = (long long)(NE + NN + NN) * 8;
    long long rows  = (long long)(NE + NN) * 8;
    int hBlocks1 = (int)((rows1 + TB - 1) / TB);
    int hBlocks  = (int)((rows + TB - 1) / TB);

    hops_kernel<<<hBlocks1, TB>>>(y,   off_lg, csr_lg, zl0, NE,
                                  x,   off_g, csr_src_g, zg0, NN,
                                  y,   off_g, csr_eid_g, pmy, NN);
    hops_kernel<<<hBlocks, TB>>>(zl0, off_lg, csr_lg, zl1, NE,
                                 zg0, off_g, csr_src_g, zg1, NN,
                                 nullptr, nullptr, nullptr, nullptr, 0);
    hops_kernel<<<hBlocks, TB>>>(zl1, off_lg, csr_lg, zlt, NE,
                                 zg1, off_g, csr_src_g, zgt, NN,
                                 nullptr, nullptr, nullptr, nullptr, 0);
    hops_kernel<<<hBlocks, TB>>>(zlt, off_lg, csr_lg, zl2, NE,
                                 zgt, off_g, csr_src_g, zg2, NN,
                                 nullptr, nullptr, nullptr, nullptr, 0);

    // ===== assemble + stats =====
    int bx = (NN + TB - 1) / TB;
    int by = (NE + TB - 1) / TB;
    assemble_both_kernel<<<bx + by, TB>>>(
        x, deg_g, pmy, zg0, zg1, zg2,
        theta_main_w, theta_main_b, theta_list_w, theta_list_b, out_x, NN, bx,
        y, deg_lg, x, pm_pd, zl0, zl1, zl2,
        gamma_main_w, gamma_main_b, gamma_list_w, gamma_list_b, out_y, NE,
        st);

    // ===== normalize =====
    normalize_both_kernel<<<512 + 2048, TB>>>(out_x, out_y, 512, st,
                                              bn_x_scale, bn_x_bias, bn_y_scale, bn_y_bias);
}

// round 5
// speedup vs baseline: 1.0228x; 1.0228x over previous
#include <cuda_runtime.h>
#include <cstddef>

#define NN   50000
#define NE   400000
#define NLE  3200000
#define F    32
#define SCAN_B 1024
#define SBG   ((NN + SCAN_B - 1) / SCAN_B)   // 49
#define SBL   ((NE + SCAN_B - 1) / SCAN_B)   // 391

typedef unsigned long long u64;

// ---------------- scratch (device globals, zero-initialized at load) ----------------
__device__ float d_zg0[NN * F];
__device__ float d_zg1[NN * F];
__device__ float d_zg2[NN * F];
__device__ float d_zgt[NN * F];
__device__ float d_pmy[NN * F];
__device__ float d_zl0[NE * F];
__device__ float d_zl1[NE * F];
__device__ float d_zl2[NE * F];
__device__ float d_zlt[NE * F];
__device__ float d_stats[128];

__device__ int d_cnt[NN + NE];          // zeroed by scan_add_cur each replay
__device__ int d_incl[NN + NE];
__device__ int d_off[(NN + 1) + (NE + 1)];
__device__ int d_rank[NE + NLE];        // intra-bucket rank per edge (g then lg)
__device__ int d_csr_src_g[NE];
__device__ int d_csr_eid_g[NE];
__device__ int d_csr_lg[NLE];
__device__ int d_bsum[1024];            // g at [0,512), lg at [512,1024)

// ---------------- f32x2 helpers ----------------
__device__ __forceinline__ u64 pack2(float a, float b) {
    u64 r; asm("mov.b64 %0, {%1, %2};" : "=l"(r) : "f"(a), "f"(b)); return r;
}
__device__ __forceinline__ void unpack2(u64 v, float& a, float& b) {
    asm("mov.b64 {%0, %1}, %2;" : "=f"(a), "=f"(b) : "l"(v));
}
__device__ __forceinline__ u64 fma2(u64 a, u64 b, u64 c) {
    u64 d; asm("fma.rn.f32x2 %0, %1, %2, %3;" : "=l"(d) : "l"(a), "l"(b), "l"(c)); return d;
}

// ================= CSR build =================
// hist also records each edge's intra-bucket rank (the atomic's return value).
__global__ void hist_both_kernel(const int* __restrict__ g_dst, const int* __restrict__ lg_dst,
                                 int* __restrict__ cnt, int* __restrict__ rank,
                                 float* __restrict__ st) {
    if (blockIdx.x == 0 && threadIdx.x < 128) st[threadIdx.x] = 0.f;
    int t = blockIdx.x * blockDim.x + threadIdx.x;
    if (t < NE) {
        rank[t] = atomicAdd(&cnt[__ldg(g_dst + t)], 1);
    } else if (t < NE + NLE) {
        rank[t] = atomicAdd(&cnt[NN + __ldg(lg_dst + (t - NE))], 1);
    }
}

// warp-shuffle inclusive scan per 1024-block; writes incl + per-block sum
__global__ void scan_block_kernel(const int* __restrict__ cnt, int* __restrict__ incl,
                                  int* __restrict__ bsum) {
    int b = blockIdx.x;
    const int* c; int* in; int n; int* bs; int rel;
    if (b < SBG) { c = cnt;      in = incl;      n = NN; bs = bsum;       rel = b; }
    else         { c = cnt + NN; in = incl + NN; n = NE; bs = bsum + 512; rel = b - SBG; }
    int tid = threadIdx.x;
    int lane = tid & 31, wid = tid >> 5;
    int i = rel * SCAN_B + tid;
    int v = (i < n) ? c[i] : 0;
    int sv = v;
#pragma unroll
    for (int o = 1; o < 32; o <<= 1) {
        int t2 = __shfl_up_sync(~0u, sv, o);
        if (lane >= o) sv += t2;
    }
    __shared__ int ws[32];
    if (lane == 31) ws[wid] = sv;
    __syncthreads();
    if (wid == 0) {
        int w = ws[lane];
#pragma unroll
        for (int o = 1; o < 32; o <<= 1) {
            int t2 = __shfl_up_sync(~0u, w, o);
            if (lane >= o) w += t2;
        }
        ws[lane] = w;
    }
    __syncthreads();
    int inc = sv + (wid ? ws[wid - 1] : 0);
    if (i < n) in[i] = inc;
    if (tid == SCAN_B - 1) bs[rel] = inc;
}

// per-block prefix over bsums; writes off; zeroes cnt for next replay
__global__ void scan_add_kernel(const int* __restrict__ incl, int* __restrict__ cnt,
                                const int* __restrict__ bsum, int* __restrict__ off) {
    int b = blockIdx.x;
    const int* in; int* c; int n; const int* bs; int rel; int* o_;
    if (b < SBG) { in = incl;      c = cnt;      n = NN; bs = bsum;       rel = b;       o_ = off; }
    else         { in = incl + NN; c = cnt + NN; n = NE; bs = bsum + 512; rel = b - SBG; o_ = off + NN + 1; }
    __shared__ int red[SCAN_B];
    int t = threadIdx.x;
    red[t] = (t < rel) ? bs[t] : 0;
    __syncthreads();
#pragma unroll
    for (int o = SCAN_B / 2; o > 0; o >>= 1) {
        if (t < o) red[t] += red[t + o];
        __syncthreads();
    }
    int prefix = red[0];
    int i = rel * SCAN_B + t;
    if (i < n) {
        o_[i + 1] = in[i] + prefix;
        c[i] = 0;                      // self-clean for next replay
        if (i == 0) o_[0] = 0;
    }
}

// atomic-free fill: p = off[dst] + rank (rank captured in hist)
__global__ void fill_both_kernel(const int* __restrict__ g_src, const int* __restrict__ g_dst,
                                 const int* __restrict__ lg_src, const int* __restrict__ lg_dst,
                                 const int* __restrict__ off_g, const int* __restrict__ off_lg,
                                 const int* __restrict__ rank,
                                 int* __restrict__ csr_src_g, int* __restrict__ csr_eid_g,
                                 int* __restrict__ csr_lg) {
    int t = blockIdx.x * blockDim.x + threadIdx.x;
    if (t < NE) {
        int p = __ldg(off_g + __ldg(g_dst + t)) + __ldg(rank + t);
        csr_src_g[p] = __ldg(g_src + t);
        csr_eid_g[p] = t;
    } else if (t < NE + NLE) {
        int e = t - NE;
        int p = __ldg(off_lg + __ldg(lg_dst + e)) + __ldg(rank + t);
        csr_lg[p] = __ldg(lg_src + e);
    }
}

// ================= pull SpMM =================
__device__ __forceinline__ void pull_row(const float* __restrict__ z, const int* __restrict__ off,
                                         const int* __restrict__ idx, float* __restrict__ out,
                                         int r, int lane) {
    int b = __ldg(off + r), e = __ldg(off + r + 1);
    float4 acc = make_float4(0.f, 0.f, 0.f, 0.f);
    int i = b;
    for (; i + 3 < e; i += 4) {
        int s0 = __ldg(idx + i), s1 = __ldg(idx + i + 1);
        int s2 = __ldg(idx + i + 2), s3 = __ldg(idx + i + 3);
        float4 v0 = *((const float4*)(z + (size_t)s0 * F) + lane);
        float4 v1 = *((const float4*)(z + (size_t)s1 * F) + lane);
        float4 v2 = *((const float4*)(z + (size_t)s2 * F) + lane);
        float4 v3 = *((const float4*)(z + (size_t)s3 * F) + lane);
        acc.x += (v0.x + v1.x) + (v2.x + v3.x);
        acc.y += (v0.y + v1.y) + (v2.y + v3.y);
        acc.z += (v0.z + v1.z) + (v2.z + v3.z);
        acc.w += (v0.w + v1.w) + (v2.w + v3.w);
    }
    for (; i < e; i++) {
        int s0 = __ldg(idx + i);
        float4 v0 = *((const float4*)(z + (size_t)s0 * F) + lane);
        acc.x += v0.x; acc.y += v0.y; acc.z += v0.z; acc.w += v0.w;
    }
    *((float4*)(out + (size_t)r * F) + lane) = acc;
}

__global__ void hops_kernel(
    const float* __restrict__ z1, const int* __restrict__ off1, const int* __restrict__ idx1,
    float* __restrict__ o1, int n1,
    const float* __restrict__ z2, const int* __restrict__ off2, const int* __restrict__ idx2,
    float* __restrict__ o2, int n2,
    const float* __restrict__ z3, const int* __restrict__ off3, const int* __restrict__ idx3,
    float* __restrict__ o3, int n3)
{
    long long t = (long long)blockIdx.x * blockDim.x + threadIdx.x;
    int r = (int)(t >> 3);
    int lane = (int)(t & 7);
    if (r < n1) {
        pull_row(z1, off1, idx1, o1, r, lane);
    } else if (r < n1 + n2) {
        pull_row(z2, off2, idx2, o2, r - n1, lane);
    } else if (r < n1 + n2 + n3) {
        pull_row(z3, off3, idx3, o3, r - n1 - n2, lane);
    }
}

// ================= fused assemble (both branches, f32x2) =================
__device__ __forceinline__ void mv_acc2(u64 acc[16], const float* __restrict__ vec,
                                        float scale, const u64 (&W)[F][16]) {
    const float4* vp = (const float4*)vec;
#pragma unroll 1
    for (int k4 = 0; k4 < 8; k4++) {
        float4 v = vp[k4];
        float c0 = v.x * scale, c1 = v.y * scale, c2 = v.z * scale, c3 = v.w * scale;
        u64 a0 = pack2(c0, c0), a1 = pack2(c1, c1), a2 = pack2(c2, c2), a3 = pack2(c3, c3);
#pragma unroll
        for (int j = 0; j < 16; j++) acc[j] = fma2(a0, W[k4 * 4 + 0][j], acc[j]);
#pragma unroll
        for (int j = 0; j < 16; j++) acc[j] = fma2(a1, W[k4 * 4 + 1][j], acc[j]);
#pragma unroll
        for (int j = 0; j < 16; j++) acc[j] = fma2(a2, W[k4 * 4 + 2][j], acc[j]);
#pragma unroll
        for (int j = 0; j < 16; j++) acc[j] = fma2(a3, W[k4 * 4 + 3][j], acc[j]);
    }
}

__global__ void assemble_both_kernel(
    const float* __restrict__ xb, const float* __restrict__ xdeg, const float* __restrict__ xextra,
    const float* __restrict__ xz0, const float* __restrict__ xz1, const float* __restrict__ xz2,
    const float* __restrict__ xWm, const float* __restrict__ xbm,
    const float* __restrict__ xWl, const float* __restrict__ xbl,
    float* __restrict__ xout, int nx, int bx,
    const float* __restrict__ yb, const float* __restrict__ ydeg, const float* __restrict__ yextra,
    const int* __restrict__ gatherIdx,
    const float* __restrict__ yz0, const float* __restrict__ yz1, const float* __restrict__ yz2,
    const float* __restrict__ yWm, const float* __restrict__ ybm,
    const float* __restrict__ yWl, const float* __restrict__ ybl,
    float* __restrict__ yout, int ny)
{
    bool isX = (int)blockIdx.x < bx;
    const float* base  = isX ? xb : yb;
    const float* deg   = isX ? xdeg : ydeg;
    const float* extra = isX ? xextra : yextra;
    const float* z0 = isX ? xz0 : yz0;
    const float* z1 = isX ? xz1 : yz1;
    const float* z2 = isX ? xz2 : yz2;
    const float* Wmain = isX ? xWm : yWm;
    const float* bmain = isX ? xbm : ybm;
    const float* Wlist = isX ? xWl : yWl;
    const float* blist = isX ? xbl : ybl;
    float* out = isX ? xout : yout;
    int n = isX ? nx : ny;
    int rblock = isX ? (int)blockIdx.x : (int)blockIdx.x - bx;

    __shared__ u64 sW[6][F][16];
    __shared__ u64 sb[16];
    for (int i = threadIdx.x; i < 6 * F * 16; i += blockDim.x) {
        int m = i >> 9;
        int rem = i & 511;
        int k = rem >> 4;
        int j2 = rem & 15;
        const float* W = (m < 3) ? (Wmain + m * 1024) : (Wlist + (m - 3) * 1024);
        sW[m][k][j2] = pack2(W[(2 * j2) * 32 + k], W[(2 * j2 + 1) * 32 + k]);
    }
    if (threadIdx.x < 16) {
        int j2 = threadIdx.x;
        float b0 = 0.f, b1 = 0.f;
#pragma unroll
        for (int m = 0; m < 3; m++) {
            b0 += bmain[m * 32 + 2 * j2] + blist[m * 32 + 2 * j2];
            b1 += bmain[m * 32 + 2 * j2 + 1] + blist[m * 32 + 2 * j2 + 1];
        }
        sb[j2] = pack2(b0, b1);
    }
    __syncthreads();

    int r = rblock * blockDim.x + threadIdx.x;
    if (r >= n) return;

    u64 acc[16];
#pragma unroll
    for (int j = 0; j < 16; j++) acc[j] = sb[j];

    size_t r32 = (size_t)r * F;
    float dg = deg[r];
    mv_acc2(acc, base + r32, 1.f, sW[0]);
    mv_acc2(acc, base + r32, dg,  sW[1]);
    const float* ex = isX ? (extra + r32) : (extra + (size_t)__ldg(gatherIdx + r) * F);
    mv_acc2(acc, ex,        1.f, sW[2]);
    mv_acc2(acc, z0 + r32,  1.f, sW[3]);
    mv_acc2(acc, z1 + r32,  1.f, sW[4]);
    mv_acc2(acc, z2 + r32,  1.f, sW[5]);

    float vals[F];
#pragma unroll
    for (int j = 0; j < 16; j++) unpack2(acc[j], vals[2 * j], vals[2 * j + 1]);
#pragma unroll
    for (int j = F / 2; j < F; j++) vals[j] = fmaxf(vals[j], 0.f);

    float4* op = (float4*)(out + r32);
#pragma unroll
    for (int j = 0; j < 8; j++)
        op[j] = make_float4(vals[4 * j], vals[4 * j + 1], vals[4 * j + 2], vals[4 * j + 3]);
}

// ================= BN stats (both outputs, one launch) =================
__global__ void stats_both_kernel(const float* __restrict__ vx, const float* __restrict__ vy,
                                  int gx, float* __restrict__ st) {
    bool isX = (int)blockIdx.x < gx;
    const float* v = isX ? vx : vy;
    long long nRows = isX ? NN : NE;
    float* s0 = st + (isX ? 0 : 64);
    int nb = isX ? gx : (gridDim.x - gx);
    int rb = isX ? (int)blockIdx.x : (int)blockIdx.x - gx;

    int col = threadIdx.x & 31;
    int w = threadIdx.x >> 5;
    int warpsPerBlock = blockDim.x >> 5;
    float s = 0.f, s2 = 0.f;
    for (long long r = (long long)rb * warpsPerBlock + w; r < nRows;
         r += (long long)nb * warpsPerBlock) {
        float val = v[r * F + col];
        s += val;
        s2 += val * val;
    }
    __shared__ float sm[2][8][F];
    sm[0][w][col] = s;
    sm[1][w][col] = s2;
    __syncthreads();
    if (threadIdx.x < F) {
        float a = 0.f, b = 0.f;
#pragma unroll
        for (int ww = 0; ww < 8; ww++) { a += sm[0][ww][threadIdx.x]; b += sm[1][ww][threadIdx.x]; }
        atomicAdd(&s0[threadIdx.x], a);
        atomicAdd(&s0[F + threadIdx.x], b);
    }
}

// ================= BN normalize =================
__global__ void normalize_both_kernel(float* __restrict__ vx, float* __restrict__ vy,
                                      int gx, const float* __restrict__ st,
                                      const float* __restrict__ sx, const float* __restrict__ bxx,
                                      const float* __restrict__ sy, const float* __restrict__ byy) {
    bool isX = (int)blockIdx.x < gx;
    float* v = isX ? vx : vy;
    long long nRows = isX ? NN : NE;
    const float* s0 = st + (isX ? 0 : 64);
    const float* scale = isX ? sx : sy;
    const float* bias  = isX ? bxx : byy;
    int nb = isX ? gx : (gridDim.x - gx);
    int rb = isX ? (int)blockIdx.x : (int)blockIdx.x - gx;

    __shared__ float mulc[F], addc[F];
    if (threadIdx.x < F) {
        float m = s0[threadIdx.x] / (float)nRows;
        float var = s0[F + threadIdx.x] / (float)nRows - m * m;
        float g = rsqrtf(var + 1e-5f) * scale[threadIdx.x];
        mulc[threadIdx.x] = g;
        addc[threadIdx.x] = bias[threadIdx.x] - m * g;
    }
    __syncthreads();
    int col = threadIdx.x & 31;
    int w = threadIdx.x >> 5;
    int warpsPerBlock = blockDim.x >> 5;
    for (long long r = (long long)rb * warpsPerBlock + w; r < nRows;
         r += (long long)nb * warpsPerBlock) {
        v[r * F + col] = fmaf(v[r * F + col], mulc[col], addc[col]);
    }
}

// ================= launcher =================
extern "C" void kernel_launch(void* const* d_in, const int* in_sizes, int n_in,
                              void* d_out, int out_size) {
    const float* x            = (const float*)d_in[0];
    const float* y            = (const float*)d_in[1];
    const float* deg_g        = (const float*)d_in[2];
    const float* deg_lg       = (const float*)d_in[3];
    const float* theta_main_w = (const float*)d_in[4];
    const float* theta_main_b = (const float*)d_in[5];
    const float* theta_list_w = (const float*)d_in[6];
    const float* theta_list_b = (const float*)d_in[7];
    const float* gamma_main_w = (const float*)d_in[8];
    const float* gamma_main_b = (const float*)d_in[9];
    const float* gamma_list_w = (const float*)d_in[10];
    const float* gamma_list_b = (const float*)d_in[11];
    const float* bn_x_scale   = (const float*)d_in[12];
    const float* bn_x_bias    = (const float*)d_in[13];
    const float* bn_y_scale   = (const float*)d_in[14];
    const float* bn_y_bias    = (const float*)d_in[15];
    const int*   g_src        = (const int*)d_in[16];
    const int*   g_dst        = (const int*)d_in[17];
    const int*   lg_src       = (const int*)d_in[18];
    const int*   lg_dst       = (const int*)d_in[19];
    const int*   pm_pd        = (const int*)d_in[20];

    float* out_x = (float*)d_out;
    float* out_y = (float*)d_out + (size_t)NN * F;

    float *zg0, *zg1, *zg2, *zgt, *pmy, *zl0, *zl1, *zl2, *zlt, *st;
    int *cnt, *incl, *off, *rank, *csr_src_g, *csr_eid_g, *csr_lg, *bsum;
    cudaGetSymbolAddress((void**)&zg0, d_zg0);
    cudaGetSymbolAddress((void**)&zg1, d_zg1);
    cudaGetSymbolAddress((void**)&zg2, d_zg2);
    cudaGetSymbolAddress((void**)&zgt, d_zgt);
    cudaGetSymbolAddress((void**)&pmy, d_pmy);
    cudaGetSymbolAddress((void**)&zl0, d_zl0);
    cudaGetSymbolAddress((void**)&zl1, d_zl1);
    cudaGetSymbolAddress((void**)&zl2, d_zl2);
    cudaGetSymbolAddress((void**)&zlt, d_zlt);
    cudaGetSymbolAddress((void**)&st,  d_stats);
    cudaGetSymbolAddress((void**)&cnt, d_cnt);
    cudaGetSymbolAddress((void**)&incl, d_incl);
    cudaGetSymbolAddress((void**)&off, d_off);
    cudaGetSymbolAddress((void**)&rank, d_rank);
    cudaGetSymbolAddress((void**)&csr_src_g, d_csr_src_g);
    cudaGetSymbolAddress((void**)&csr_eid_g, d_csr_eid_g);
    cudaGetSymbolAddress((void**)&csr_lg, d_csr_lg);
    cudaGetSymbolAddress((void**)&bsum, d_bsum);

    int* off_g  = off;
    int* off_lg = off + NN + 1;

    const int TB = 256;
    int eBlocks = (NE + NLE + TB - 1) / TB;

    // ===== CSR build (rank-based, atomic-free fill) =====
    hist_both_kernel<<<eBlocks, TB>>>(g_dst, lg_dst, cnt, rank, st);
    scan_block_kernel<<<SBG + SBL, SCAN_B>>>(cnt, incl, bsum);
    scan_add_kernel<<<SBG + SBL, SCAN_B>>>(incl, cnt, bsum, off);
    fill_both_kernel<<<eBlocks, TB>>>(g_src, g_dst, lg_src, lg_dst,
                                      off_g, off_lg, rank,
                                      csr_src_g, csr_eid_g, csr_lg);

    // ===== hops =====
    long long rows1 = (long long)(NE + NN + NN) * 8;
    long long rows  = (long long)(NE + NN) * 8;
    int hBlocks1 = (int)((rows1 + TB - 1) / TB);
    int hBlocks  = (int)((rows + TB - 1) / TB);

    hops_kernel<<<hBlocks1, TB>>>(y,   off_lg, csr_lg, zl0, NE,
                                  x,   off_g, csr_src_g, zg0, NN,
                                  y,   off_g, csr_eid_g, pmy, NN);
    hops_kernel<<<hBlocks, TB>>>(zl0, off_lg, csr_lg, zl1, NE,
                                 zg0, off_g, csr_src_g, zg1, NN,
                                 nullptr, nullptr, nullptr, nullptr, 0);
    hops_kernel<<<hBlocks, TB>>>(zl1, off_lg, csr_lg, zlt, NE,
                                 zg1, off_g, csr_src_g, zgt, NN,
                                 nullptr, nullptr, nullptr, nullptr, 0);
    hops_kernel<<<hBlocks, TB>>>(zlt, off_lg, csr_lg, zl2, NE,
                                 zgt, off_g, csr_src_g, zg2, NN,
                                 nullptr, nullptr, nullptr, nullptr, 0);

    // ===== assemble =====
    int bx = (NN + TB - 1) / TB;
    int by = (NE + TB - 1) / TB;
    assemble_both_kernel<<<bx + by, TB>>>(
        x, deg_g, pmy, zg0, zg1, zg2,
        theta_main_w, theta_main_b, theta_list_w, theta_list_b, out_x, NN, bx,
        y, deg_lg, x, pm_pd, zl0, zl1, zl2,
        gamma_main_w, gamma_main_b, gamma_list_w, gamma_list_b, out_y, NE);

    // ===== batchnorm =====
    stats_both_kernel<<<512 + 2048, TB>>>(out_x, out_y, 512, st);
    normalize_both_kernel<<<512 + 2048, TB>>>(out_x, out_y, 512, st,
                                              bn_x_scale, bn_x_bias, bn_y_scale, bn_y_bias);
}

// round 6
// speedup vs baseline: 1.0331x; 1.0100x over previous
#include <cuda_runtime.h>
#include <cstddef>

#define NN   50000
#define NE   400000
#define NLE  3200000
#define F    32
#define SCAN_B 1024
#define SBG   ((NN + SCAN_B - 1) / SCAN_B)   // 49
#define SBL   ((NE + SCAN_B - 1) / SCAN_B)   // 391

typedef unsigned long long u64;

// ---------------- scratch (device globals, zero-initialized at load) ----------------
__device__ float d_zg0[NN * F];
__device__ float d_zg1[NN * F];
__device__ float d_zg2[NN * F];
__device__ float d_zgt[NN * F];
__device__ float d_pmy[NN * F];
__device__ float d_zl0[NE * F];
__device__ float d_zl1[NE * F];
__device__ float d_zl2[NE * F];
__device__ float d_zlt[NE * F];
__device__ float d_stats[128];

__device__ int d_cnt[NN + NE];          // zeroed by scan_add each replay
__device__ int d_incl[NN + NE];
__device__ int d_off[(NN + 1) + (NE + 1)];
__device__ int d_rank[NE + NLE];
__device__ int d_csr_src_g[NE];
__device__ int d_csr_eid_g[NE];
__device__ int d_csr_lg[NLE];
__device__ int d_bsum[1024];

// ---------------- f32x2 helpers ----------------
__device__ __forceinline__ u64 pack2(float a, float b) {
    u64 r; asm("mov.b64 %0, {%1, %2};" : "=l"(r) : "f"(a), "f"(b)); return r;
}
__device__ __forceinline__ void unpack2(u64 v, float& a, float& b) {
    asm("mov.b64 {%0, %1}, %2;" : "=f"(a), "=f"(b) : "l"(v));
}
__device__ __forceinline__ u64 fma2(u64 a, u64 b, u64 c) {
    u64 d; asm("fma.rn.f32x2 %0, %1, %2, %3;" : "=l"(d) : "l"(a), "l"(b), "l"(c)); return d;
}

// ================= CSR build =================
__global__ void hist_both_kernel(const int* __restrict__ g_dst, const int* __restrict__ lg_dst,
                                 int* __restrict__ cnt, int* __restrict__ rank,
                                 float* __restrict__ st) {
    if (blockIdx.x == 0 && threadIdx.x < 128) st[threadIdx.x] = 0.f;
    int t = blockIdx.x * blockDim.x + threadIdx.x;
    if (t < NE) {
        int r = atomicAdd(&cnt[__ldg(g_dst + t)], 1);
        __stcs(rank + t, r);                                   // evict-first: read once next kernel
    } else if (t < NE + NLE) {
        int r = atomicAdd(&cnt[NN + __ldg(lg_dst + (t - NE))], 1);
        __stcs(rank + t, r);
    }
}

__global__ void scan_block_kernel(const int* __restrict__ cnt, int* __restrict__ incl,
                                  int* __restrict__ bsum) {
    int b = blockIdx.x;
    const int* c; int* in; int n; int* bs; int rel;
    if (b < SBG) { c = cnt;      in = incl;      n = NN; bs = bsum;       rel = b; }
    else         { c = cnt + NN; in = incl + NN; n = NE; bs = bsum + 512; rel = b - SBG; }
    int tid = threadIdx.x;
    int lane = tid & 31, wid = tid >> 5;
    int i = rel * SCAN_B + tid;
    int v = (i < n) ? c[i] : 0;
    int sv = v;
#pragma unroll
    for (int o = 1; o < 32; o <<= 1) {
        int t2 = __shfl_up_sync(~0u, sv, o);
        if (lane >= o) sv += t2;
    }
    __shared__ int ws[32];
    if (lane == 31) ws[wid] = sv;
    __syncthreads();
    if (wid == 0) {
        int w = ws[lane];
#pragma unroll
        for (int o = 1; o < 32; o <<= 1) {
            int t2 = __shfl_up_sync(~0u, w, o);
            if (lane >= o) w += t2;
        }
        ws[lane] = w;
    }
    __syncthreads();
    int inc = sv + (wid ? ws[wid - 1] : 0);
    if (i < n) in[i] = inc;
    if (tid == SCAN_B - 1) bs[rel] = inc;
}

__global__ void scan_add_kernel(const int* __restrict__ incl, int* __restrict__ cnt,
                                const int* __restrict__ bsum, int* __restrict__ off) {
    int b = blockIdx.x;
    const int* in; int* c; int n; const int* bs; int rel; int* o_;
    if (b < SBG) { in = incl;      c = cnt;      n = NN; bs = bsum;       rel = b;       o_ = off; }
    else         { in = incl + NN; c = cnt + NN; n = NE; bs = bsum + 512; rel = b - SBG; o_ = off + NN + 1; }
    __shared__ int red[SCAN_B];
    int t = threadIdx.x;
    red[t] = (t < rel) ? bs[t] : 0;
    __syncthreads();
#pragma unroll
    for (int o = SCAN_B / 2; o > 0; o >>= 1) {
        if (t < o) red[t] += red[t + o];
        __syncthreads();
    }
    int prefix = red[0];
    int i = rel * SCAN_B + t;
    if (i < n) {
        o_[i + 1] = in[i] + prefix;
        c[i] = 0;
        if (i == 0) o_[0] = 0;
    }
}

__global__ void fill_both_kernel(const int* __restrict__ g_src, const int* __restrict__ g_dst,
                                 const int* __restrict__ lg_src, const int* __restrict__ lg_dst,
                                 const int* __restrict__ off_g, const int* __restrict__ off_lg,
                                 const int* __restrict__ rank,
                                 int* __restrict__ csr_src_g, int* __restrict__ csr_eid_g,
                                 int* __restrict__ csr_lg) {
    int t = blockIdx.x * blockDim.x + threadIdx.x;
    if (t < NE) {
        int p = __ldg(off_g + __ldg(g_dst + t)) + __ldcs(rank + t);
        __stcs(csr_src_g + p, __ldg(g_src + t));
        __stcs(csr_eid_g + p, t);
    } else if (t < NE + NLE) {
        int e = t - NE;
        int p = __ldg(off_lg + __ldg(lg_dst + e)) + __ldcs(rank + t);
        __stcs(csr_lg + p, __ldg(lg_src + e));
    }
}

// ================= pull SpMM =================
__device__ __forceinline__ void pull_row(const float* __restrict__ z, const int* __restrict__ off,
                                         const int* __restrict__ idx, float* __restrict__ out,
                                         int r, int lane) {
    int b = __ldg(off + r), e = __ldg(off + r + 1);
    float4 acc = make_float4(0.f, 0.f, 0.f, 0.f);
    int i = b;
    for (; i + 3 < e; i += 4) {
        int s0 = __ldg(idx + i), s1 = __ldg(idx + i + 1);
        int s2 = __ldg(idx + i + 2), s3 = __ldg(idx + i + 3);
        float4 v0 = *((const float4*)(z + (size_t)s0 * F) + lane);
        float4 v1 = *((const float4*)(z + (size_t)s1 * F) + lane);
        float4 v2 = *((const float4*)(z + (size_t)s2 * F) + lane);
        float4 v3 = *((const float4*)(z + (size_t)s3 * F) + lane);
        acc.x += (v0.x + v1.x) + (v2.x + v3.x);
        acc.y += (v0.y + v1.y) + (v2.y + v3.y);
        acc.z += (v0.z + v1.z) + (v2.z + v3.z);
        acc.w += (v0.w + v1.w) + (v2.w + v3.w);
    }
    for (; i < e; i++) {
        int s0 = __ldg(idx + i);
        float4 v0 = *((const float4*)(z + (size_t)s0 * F) + lane);
        acc.x += v0.x; acc.y += v0.y; acc.z += v0.z; acc.w += v0.w;
    }
    // evict-first store: keep the gather source resident in L2
    __stcs((float4*)(out + (size_t)r * F) + lane, acc);
}

__global__ void hops_kernel(
    const float* __restrict__ z1, const int* __restrict__ off1, const int* __restrict__ idx1,
    float* __restrict__ o1, int n1,
    const float* __restrict__ z2, const int* __restrict__ off2, const int* __restrict__ idx2,
    float* __restrict__ o2, int n2,
    const float* __restrict__ z3, const int* __restrict__ off3, const int* __restrict__ idx3,
    float* __restrict__ o3, int n3)
{
    long long t = (long long)blockIdx.x * blockDim.x + threadIdx.x;
    int r = (int)(t >> 3);
    int lane = (int)(t & 7);
    if (r < n1) {
        pull_row(z1, off1, idx1, o1, r, lane);
    } else if (r < n1 + n2) {
        pull_row(z2, off2, idx2, o2, r - n1, lane);
    } else if (r < n1 + n2 + n3) {
        pull_row(z3, off3, idx3, o3, r - n1 - n2, lane);
    }
}

// ================= fused assemble (both branches, f32x2) =================
__device__ __forceinline__ void mv_acc2(u64 acc[16], const float* __restrict__ vec,
                                        float scale, const u64 (&W)[F][16], bool streaming) {
#pragma unroll 1
    for (int k4 = 0; k4 < 8; k4++) {
        float4 v = streaming ? __ldcs((const float4*)vec + k4) : *((const float4*)vec + k4);
        float c0 = v.x * scale, c1 = v.y * scale, c2 = v.z * scale, c3 = v.w * scale;
        u64 a0 = pack2(c0, c0), a1 = pack2(c1, c1), a2 = pack2(c2, c2), a3 = pack2(c3, c3);
#pragma unroll
        for (int j = 0; j < 16; j++) acc[j] = fma2(a0, W[k4 * 4 + 0][j], acc[j]);
#pragma unroll
        for (int j = 0; j < 16; j++) acc[j] = fma2(a1, W[k4 * 4 + 1][j], acc[j]);
#pragma unroll
        for (int j = 0; j < 16; j++) acc[j] = fma2(a2, W[k4 * 4 + 2][j], acc[j]);
#pragma unroll
        for (int j = 0; j < 16; j++) acc[j] = fma2(a3, W[k4 * 4 + 3][j], acc[j]);
    }
}

__global__ void assemble_both_kernel(
    const float* __restrict__ xb, const float* __restrict__ xdeg, const float* __restrict__ xextra,
    const float* __restrict__ xz0, const float* __restrict__ xz1, const float* __restrict__ xz2,
    const float* __restrict__ xWm, const float* __restrict__ xbm,
    const float* __restrict__ xWl, const float* __restrict__ xbl,
    float* __restrict__ xout, int nx, int bx,
    const float* __restrict__ yb, const float* __restrict__ ydeg, const float* __restrict__ yextra,
    const int* __restrict__ gatherIdx,
    const float* __restrict__ yz0, const float* __restrict__ yz1, const float* __restrict__ yz2,
    const float* __restrict__ yWm, const float* __restrict__ ybm,
    const float* __restrict__ yWl, const float* __restrict__ ybl,
    float* __restrict__ yout, int ny)
{
    bool isX = (int)blockIdx.x < bx;
    const float* base  = isX ? xb : yb;
    const float* deg   = isX ? xdeg : ydeg;
    const float* extra = isX ? xextra : yextra;
    const float* z0 = isX ? xz0 : yz0;
    const float* z1 = isX ? xz1 : yz1;
    const float* z2 = isX ? xz2 : yz2;
    const float* Wmain = isX ? xWm : yWm;
    const float* bmain = isX ? xbm : ybm;
    const float* Wlist = isX ? xWl : yWl;
    const float* blist = isX ? xbl : ybl;
    float* out = isX ? xout : yout;
    int n = isX ? nx : ny;
    int rblock = isX ? (int)blockIdx.x : (int)blockIdx.x - bx;

    __shared__ u64 sW[6][F][16];
    __shared__ u64 sb[16];
    for (int i = threadIdx.x; i < 6 * F * 16; i += blockDim.x) {
        int m = i >> 9;
        int rem = i & 511;
        int k = rem >> 4;
        int j2 = rem & 15;
        const float* W = (m < 3) ? (Wmain + m * 1024) : (Wlist + (m - 3) * 1024);
        sW[m][k][j2] = pack2(W[(2 * j2) * 32 + k], W[(2 * j2 + 1) * 32 + k]);
    }
    if (threadIdx.x < 16) {
        int j2 = threadIdx.x;
        float b0 = 0.f, b1 = 0.f;
#pragma unroll
        for (int m = 0; m < 3; m++) {
            b0 += bmain[m * 32 + 2 * j2] + blist[m * 32 + 2 * j2];
            b1 += bmain[m * 32 + 2 * j2 + 1] + blist[m * 32 + 2 * j2 + 1];
        }
        sb[j2] = pack2(b0, b1);
    }
    __syncthreads();

    int r = rblock * blockDim.x + threadIdx.x;
    if (r >= n) return;

    u64 acc[16];
#pragma unroll
    for (int j = 0; j < 16; j++) acc[j] = sb[j];

    size_t r32 = (size_t)r * F;
    float dg = deg[r];
    mv_acc2(acc, base + r32, 1.f, sW[0], false);
    mv_acc2(acc, base + r32, dg,  sW[1], false);
    const float* ex = isX ? (extra + r32) : (extra + (size_t)__ldg(gatherIdx + r) * F);
    mv_acc2(acc, ex,        1.f, sW[2], false);
    mv_acc2(acc, z0 + r32,  1.f, sW[3], true);
    mv_acc2(acc, z1 + r32,  1.f, sW[4], true);
    mv_acc2(acc, z2 + r32,  1.f, sW[5], true);

    float vals[F];
#pragma unroll
    for (int j = 0; j < 16; j++) unpack2(acc[j], vals[2 * j], vals[2 * j + 1]);
#pragma unroll
    for (int j = F / 2; j < F; j++) vals[j] = fmaxf(vals[j], 0.f);

    float4* op = (float4*)(out + r32);
#pragma unroll
    for (int j = 0; j < 8; j++)
        op[j] = make_float4(vals[4 * j], vals[4 * j + 1], vals[4 * j + 2], vals[4 * j + 3]);
}

// ================= BN stats =================
__global__ void stats_both_kernel(const float* __restrict__ vx, const float* __restrict__ vy,
                                  int gx, float* __restrict__ st) {
    bool isX = (int)blockIdx.x < gx;
    const float* v = isX ? vx : vy;
    long long nRows = isX ? NN : NE;
    float* s0 = st + (isX ? 0 : 64);
    int nb = isX ? gx : (gridDim.x - gx);
    int rb = isX ? (int)blockIdx.x : (int)blockIdx.x - gx;

    int col = threadIdx.x & 31;
    int w = threadIdx.x >> 5;
    int warpsPerBlock = blockDim.x >> 5;
    float s = 0.f, s2 = 0.f;
    for (long long r = (long long)rb * warpsPerBlock + w; r < nRows;
         r += (long long)nb * warpsPerBlock) {
        float val = v[r * F + col];
        s += val;
        s2 += val * val;
    }
    __shared__ float sm[2][8][F];
    sm[0][w][col] = s;
    sm[1][w][col] = s2;
    __syncthreads();
    if (threadIdx.x < F) {
        float a = 0.f, b = 0.f;
#pragma unroll
        for (int ww = 0; ww < 8; ww++) { a += sm[0][ww][threadIdx.x]; b += sm[1][ww][threadIdx.x]; }
        atomicAdd(&s0[threadIdx.x], a);
        atomicAdd(&s0[F + threadIdx.x], b);
    }
}

// ================= BN normalize =================
__global__ void normalize_both_kernel(float* __restrict__ vx, float* __restrict__ vy,
                                      int gx, const float* __restrict__ st,
                                      const float* __restrict__ sx, const float* __restrict__ bxx,
                                      const float* __restrict__ sy, const float* __restrict__ byy) {
    bool isX = (int)blockIdx.x < gx;
    float* v = isX ? vx : vy;
    long long nRows = isX ? NN : NE;
    const float* s0 = st + (isX ? 0 : 64);
    const float* scale = isX ? sx : sy;
    const float* bias  = isX ? bxx : byy;
    int nb = isX ? gx : (gridDim.x - gx);
    int rb = isX ? (int)blockIdx.x : (int)blockIdx.x - gx;

    __shared__ float mulc[F], addc[F];
    if (threadIdx.x < F) {
        float m = s0[threadIdx.x] / (float)nRows;
        float var = s0[F + threadIdx.x] / (float)nRows - m * m;
        float g = rsqrtf(var + 1e-5f) * scale[threadIdx.x];
        mulc[threadIdx.x] = g;
        addc[threadIdx.x] = bias[threadIdx.x] - m * g;
    }
    __syncthreads();
    int col = threadIdx.x & 31;
    int w = threadIdx.x >> 5;
    int warpsPerBlock = blockDim.x >> 5;
    for (long long r = (long long)rb * warpsPerBlock + w; r < nRows;
         r += (long long)nb * warpsPerBlock) {
        v[r * F + col] = fmaf(v[r * F + col], mulc[col], addc[col]);
    }
}

// ================= launcher =================
extern "C" void kernel_launch(void* const* d_in, const int* in_sizes, int n_in,
                              void* d_out, int out_size) {
    const float* x            = (const float*)d_in[0];
    const float* y            = (const float*)d_in[1];
    const float* deg_g        = (const float*)d_in[2];
    const float* deg_lg       = (const float*)d_in[3];
    const float* theta_main_w = (const float*)d_in[4];
    const float* theta_main_b = (const float*)d_in[5];
    const float* theta_list_w = (const float*)d_in[6];
    const float* theta_list_b = (const float*)d_in[7];
    const float* gamma_main_w = (const float*)d_in[8];
    const float* gamma_main_b = (const float*)d_in[9];
    const float* gamma_list_w = (const float*)d_in[10];
    const float* gamma_list_b = (const float*)d_in[11];
    const float* bn_x_scale   = (const float*)d_in[12];
    const float* bn_x_bias    = (const float*)d_in[13];
    const float* bn_y_scale   = (const float*)d_in[14];
    const float* bn_y_bias    = (const float*)d_in[15];
    const int*   g_src        = (const int*)d_in[16];
    const int*   g_dst        = (const int*)d_in[17];
    const int*   lg_src       = (const int*)d_in[18];
    const int*   lg_dst       = (const int*)d_in[19];
    const int*   pm_pd        = (const int*)d_in[20];

    float* out_x = (float*)d_out;
    float* out_y = (float*)d_out + (size_t)NN * F;

    float *zg0, *zg1, *zg2, *zgt, *pmy, *zl0, *zl1, *zl2, *zlt, *st;
    int *cnt, *incl, *off, *rank, *csr_src_g, *csr_eid_g, *csr_lg, *bsum;
    cudaGetSymbolAddress((void**)&zg0, d_zg0);
    cudaGetSymbolAddress((void**)&zg1, d_zg1);
    cudaGetSymbolAddress((void**)&zg2, d_zg2);
    cudaGetSymbolAddress((void**)&zgt, d_zgt);
    cudaGetSymbolAddress((void**)&pmy, d_pmy);
    cudaGetSymbolAddress((void**)&zl0, d_zl0);
    cudaGetSymbolAddress((void**)&zl1, d_zl1);
    cudaGetSymbolAddress((void**)&zl2, d_zl2);
    cudaGetSymbolAddress((void**)&zlt, d_zlt);
    cudaGetSymbolAddress((void**)&st,  d_stats);
    cudaGetSymbolAddress((void**)&cnt, d_cnt);
    cudaGetSymbolAddress((void**)&incl, d_incl);
    cudaGetSymbolAddress((void**)&off, d_off);
    cudaGetSymbolAddress((void**)&rank, d_rank);
    cudaGetSymbolAddress((void**)&csr_src_g, d_csr_src_g);
    cudaGetSymbolAddress((void**)&csr_eid_g, d_csr_eid_g);
    cudaGetSymbolAddress((void**)&csr_lg, d_csr_lg);
    cudaGetSymbolAddress((void**)&bsum, d_bsum);

    int* off_g  = off;
    int* off_lg = off + NN + 1;

    const int TB = 256;
    int eBlocks = (NE + NLE + TB - 1) / TB;

    // ===== CSR build =====
    hist_both_kernel<<<eBlocks, TB>>>(g_dst, lg_dst, cnt, rank, st);
    scan_block_kernel<<<SBG + SBL, SCAN_B>>>(cnt, incl, bsum);
    scan_add_kernel<<<SBG + SBL, SCAN_B>>>(incl, cnt, bsum, off);
    fill_both_kernel<<<eBlocks, TB>>>(g_src, g_dst, lg_src, lg_dst,
                                      off_g, off_lg, rank,
                                      csr_src_g, csr_eid_g, csr_lg);

    // ===== hops =====
    long long rows1 = (long long)(NE + NN + NN) * 8;
    long long rows  = (long long)(NE + NN) * 8;
    int hBlocks1 = (int)((rows1 + TB - 1) / TB);
    int hBlocks  = (int)((rows + TB - 1) / TB);

    hops_kernel<<<hBlocks1, TB>>>(y,   off_lg, csr_lg, zl0, NE,
                                  x,   off_g, csr_src_g, zg0, NN,
                                  y,   off_g, csr_eid_g, pmy, NN);
    hops_kernel<<<hBlocks, TB>>>(zl0, off_lg, csr_lg, zl1, NE,
                                 zg0, off_g, csr_src_g, zg1, NN,
                                 nullptr, nullptr, nullptr, nullptr, 0);
    hops_kernel<<<hBlocks, TB>>>(zl1, off_lg, csr_lg, zlt, NE,
                                 zg1, off_g, csr_src_g, zgt, NN,
                                 nullptr, nullptr, nullptr, nullptr, 0);
    hops_kernel<<<hBlocks, TB>>>(zlt, off_lg, csr_lg, zl2, NE,
                                 zgt, off_g, csr_src_g, zg2, NN,
                                 nullptr, nullptr, nullptr, nullptr, 0);

    // ===== assemble =====
    int bx = (NN + TB - 1) / TB;
    int by = (NE + TB - 1) / TB;
    assemble_both_kernel<<<bx + by, TB>>>(
        x, deg_g, pmy, zg0, zg1, zg2,
        theta_main_w, theta_main_b, theta_list_w, theta_list_b, out_x, NN, bx,
        y, deg_lg, x, pm_pd, zl0, zl1, zl2,
        gamma_main_w, gamma_main_b, gamma_list_w, gamma_list_b, out_y, NE);

    // ===== batchnorm =====
    stats_both_kernel<<<512 + 2048, TB>>>(out_x, out_y, 512, st);
    normalize_both_kernel<<<512 + 2048, TB>>>(out_x, out_y, 512, st,
                                              bn_x_scale, bn_x_bias, bn_y_scale, bn_y_bias);
}

// round 7
// speedup vs baseline: 1.1058x; 1.0704x over previous
#include <cuda_runtime.h>
#include <cuda_fp16.h>
#include <cstddef>

#define NN   50000
#define NE   400000
#define NLE  3200000
#define F    32
#define SCAN_B 1024
#define SBG   ((NN + SCAN_B - 1) / SCAN_B)   // 49
#define SBL   ((NE + SCAN_B - 1) / SCAN_B)   // 391

typedef unsigned long long u64;

// ---------------- scratch (device globals) ----------------
__device__ float d_zg0[NN * F];
__device__ float d_zg1[NN * F];
__device__ float d_zg2[NN * F];
__device__ float d_zgt[NN * F];
__device__ float d_pmy[NN * F];
// lg hop intermediates in fp16: row = 32 halfs = 8 uint2 (8B aligned)
__device__ uint2 d_zl0[NE * F / 4];
__device__ uint2 d_zl1[NE * F / 4];
__device__ uint2 d_zl2[NE * F / 4];
__device__ uint2 d_zlt[NE * F / 4];
__device__ float d_stats[128];

__device__ int d_cnt[NN + NE];
__device__ int d_incl[NN + NE];
__device__ int d_off[(NN + 1) + (NE + 1)];
__device__ int d_rank[NE + NLE];
__device__ int d_csr_src_g[NE];
__device__ int d_csr_eid_g[NE];
__device__ int d_csr_lg[NLE];
__device__ int d_bsum[1024];

// ---------------- f32x2 helpers ----------------
__device__ __forceinline__ u64 pack2(float a, float b) {
    u64 r; asm("mov.b64 %0, {%1, %2};" : "=l"(r) : "f"(a), "f"(b)); return r;
}
__device__ __forceinline__ void unpack2(u64 v, float& a, float& b) {
    asm("mov.b64 {%0, %1}, %2;" : "=f"(a), "=f"(b) : "l"(v));
}
__device__ __forceinline__ u64 fma2(u64 a, u64 b, u64 c) {
    u64 d; asm("fma.rn.f32x2 %0, %1, %2, %3;" : "=l"(d) : "l"(a), "l"(b), "l"(c)); return d;
}

// ================= CSR build =================
__global__ void hist_both_kernel(const int* __restrict__ g_dst, const int* __restrict__ lg_dst,
                                 int* __restrict__ cnt, int* __restrict__ rank,
                                 float* __restrict__ st) {
    if (blockIdx.x == 0 && threadIdx.x < 128) st[threadIdx.x] = 0.f;
    int t = blockIdx.x * blockDim.x + threadIdx.x;
    if (t < NE) {
        int r = atomicAdd(&cnt[__ldg(g_dst + t)], 1);
        __stcs(rank + t, r);
    } else if (t < NE + NLE) {
        int r = atomicAdd(&cnt[NN + __ldg(lg_dst + (t - NE))], 1);
        __stcs(rank + t, r);
    }
}

__global__ void scan_block_kernel(const int* __restrict__ cnt, int* __restrict__ incl,
                                  int* __restrict__ bsum) {
    int b = blockIdx.x;
    const int* c; int* in; int n; int* bs; int rel;
    if (b < SBG) { c = cnt;      in = incl;      n = NN; bs = bsum;       rel = b; }
    else         { c = cnt + NN; in = incl + NN; n = NE; bs = bsum + 512; rel = b - SBG; }
    int tid = threadIdx.x;
    int lane = tid & 31, wid = tid >> 5;
    int i = rel * SCAN_B + tid;
    int v = (i < n) ? c[i] : 0;
    int sv = v;
#pragma unroll
    for (int o = 1; o < 32; o <<= 1) {
        int t2 = __shfl_up_sync(~0u, sv, o);
        if (lane >= o) sv += t2;
    }
    __shared__ int ws[32];
    if (lane == 31) ws[wid] = sv;
    __syncthreads();
    if (wid == 0) {
        int w = ws[lane];
#pragma unroll
        for (int o = 1; o < 32; o <<= 1) {
            int t2 = __shfl_up_sync(~0u, w, o);
            if (lane >= o) w += t2;
        }
        ws[lane] = w;
    }
    __syncthreads();
    int inc = sv + (wid ? ws[wid - 1] : 0);
    if (i < n) in[i] = inc;
    if (tid == SCAN_B - 1) bs[rel] = inc;
}

__global__ void scan_add_kernel(const int* __restrict__ incl, int* __restrict__ cnt,
                                const int* __restrict__ bsum, int* __restrict__ off) {
    int b = blockIdx.x;
    const int* in; int* c; int n; const int* bs; int rel; int* o_;
    if (b < SBG) { in = incl;      c = cnt;      n = NN; bs = bsum;       rel = b;       o_ = off; }
    else         { in = incl + NN; c = cnt + NN; n = NE; bs = bsum + 512; rel = b - SBG; o_ = off + NN + 1; }
    __shared__ int red[SCAN_B];
    int t = threadIdx.x;
    red[t] = (t < rel) ? bs[t] : 0;
    __syncthreads();
#pragma unroll
    for (int o = SCAN_B / 2; o > 0; o >>= 1) {
        if (t < o) red[t] += red[t + o];
        __syncthreads();
    }
    int prefix = red[0];
    int i = rel * SCAN_B + t;
    if (i < n) {
        o_[i + 1] = in[i] + prefix;
        c[i] = 0;
        if (i == 0) o_[0] = 0;
    }
}

__global__ void fill_both_kernel(const int* __restrict__ g_src, const int* __restrict__ g_dst,
                                 const int* __restrict__ lg_src, const int* __restrict__ lg_dst,
                                 const int* __restrict__ off_g, const int* __restrict__ off_lg,
                                 const int* __restrict__ rank,
                                 int* __restrict__ csr_src_g, int* __restrict__ csr_eid_g,
                                 int* __restrict__ csr_lg) {
    int t = blockIdx.x * blockDim.x + threadIdx.x;
    if (t < NE) {
        int p = __ldg(off_g + __ldg(g_dst + t)) + __ldcs(rank + t);
        __stcs(csr_src_g + p, __ldg(g_src + t));
        __stcs(csr_eid_g + p, t);
    } else if (t < NE + NLE) {
        int e = t - NE;
        int p = __ldg(off_lg + __ldg(lg_dst + e)) + __ldcs(rank + t);
        __stcs(csr_lg + p, __ldg(lg_src + e));
    }
}

// ================= pull SpMM variants =================
// fp32 src -> fp32 out (g branch)
__device__ __forceinline__ void pull_f32_f32(const float* __restrict__ z, const int* __restrict__ off,
                                             const int* __restrict__ idx, float* __restrict__ out,
                                             int r, int lane) {
    int b = __ldg(off + r), e = __ldg(off + r + 1);
    float4 acc = make_float4(0.f, 0.f, 0.f, 0.f);
    int i = b;
    for (; i + 3 < e; i += 4) {
        int s0 = __ldg(idx + i), s1 = __ldg(idx + i + 1);
        int s2 = __ldg(idx + i + 2), s3 = __ldg(idx + i + 3);
        float4 v0 = *((const float4*)(z + (size_t)s0 * F) + lane);
        float4 v1 = *((const float4*)(z + (size_t)s1 * F) + lane);
        float4 v2 = *((const float4*)(z + (size_t)s2 * F) + lane);
        float4 v3 = *((const float4*)(z + (size_t)s3 * F) + lane);
        acc.x += (v0.x + v1.x) + (v2.x + v3.x);
        acc.y += (v0.y + v1.y) + (v2.y + v3.y);
        acc.z += (v0.z + v1.z) + (v2.z + v3.z);
        acc.w += (v0.w + v1.w) + (v2.w + v3.w);
    }
    for (; i < e; i++) {
        int s0 = __ldg(idx + i);
        float4 v0 = *((const float4*)(z + (size_t)s0 * F) + lane);
        acc.x += v0.x; acc.y += v0.y; acc.z += v0.z; acc.w += v0.w;
    }
    __stcs((float4*)(out + (size_t)r * F) + lane, acc);
}

__device__ __forceinline__ uint2 f4_to_h(float4 a) {
    __half2 h0 = __floats2half2_rn(a.x, a.y);
    __half2 h1 = __floats2half2_rn(a.z, a.w);
    uint2 u;
    u.x = *(unsigned int*)&h0;
    u.y = *(unsigned int*)&h1;
    return u;
}
__device__ __forceinline__ void h_acc(float4& acc, uint2 v) {
    __half2 h0 = *(__half2*)&v.x;
    __half2 h1 = *(__half2*)&v.y;
    float2 f0 = __half22float2(h0);
    float2 f1 = __half22float2(h1);
    acc.x += f0.x; acc.y += f0.y; acc.z += f1.x; acc.w += f1.y;
}

// fp32 src -> half out (lg hop 1)
__device__ __forceinline__ void pull_f32_h(const float* __restrict__ z, const int* __restrict__ off,
                                           const int* __restrict__ idx, uint2* __restrict__ out,
                                           int r, int lane) {
    int b = __ldg(off + r), e = __ldg(off + r + 1);
    float4 acc = make_float4(0.f, 0.f, 0.f, 0.f);
    int i = b;
    for (; i + 3 < e; i += 4) {
        int s0 = __ldg(idx + i), s1 = __ldg(idx + i + 1);
        int s2 = __ldg(idx + i + 2), s3 = __ldg(idx + i + 3);
        float4 v0 = *((const float4*)(z + (size_t)s0 * F) + lane);
        float4 v1 = *((const float4*)(z + (size_t)s1 * F) + lane);
        float4 v2 = *((const float4*)(z + (size_t)s2 * F) + lane);
        float4 v3 = *((const float4*)(z + (size_t)s3 * F) + lane);
        acc.x += (v0.x + v1.x) + (v2.x + v3.x);
        acc.y += (v0.y + v1.y) + (v2.y + v3.y);
        acc.z += (v0.z + v1.z) + (v2.z + v3.z);
        acc.w += (v0.w + v1.w) + (v2.w + v3.w);
    }
    for (; i < e; i++) {
        int s0 = __ldg(idx + i);
        float4 v0 = *((const float4*)(z + (size_t)s0 * F) + lane);
        acc.x += v0.x; acc.y += v0.y; acc.z += v0.z; acc.w += v0.w;
    }
    __stcs(out + (size_t)r * 8 + lane, f4_to_h(acc));
}

// half src -> half out (lg hops 2-4)
__device__ __forceinline__ void pull_h_h(const uint2* __restrict__ z, const int* __restrict__ off,
                                         const int* __restrict__ idx, uint2* __restrict__ out,
                                         int r, int lane) {
    int b = __ldg(off + r), e = __ldg(off + r + 1);
    float4 acc = make_float4(0.f, 0.f, 0.f, 0.f);
    int i = b;
    for (; i + 3 < e; i += 4) {
        int s0 = __ldg(idx + i), s1 = __ldg(idx + i + 1);
        int s2 = __ldg(idx + i + 2), s3 = __ldg(idx + i + 3);
        uint2 v0 = z[(size_t)s0 * 8 + lane];
        uint2 v1 = z[(size_t)s1 * 8 + lane];
        uint2 v2 = z[(size_t)s2 * 8 + lane];
        uint2 v3 = z[(size_t)s3 * 8 + lane];
        h_acc(acc, v0); h_acc(acc, v1); h_acc(acc, v2); h_acc(acc, v3);
    }
    for (; i < e; i++) {
        int s0 = __ldg(idx + i);
        h_acc(acc, z[(size_t)s0 * 8 + lane]);
    }
    __stcs(out + (size_t)r * 8 + lane, f4_to_h(acc));
}

// mode 0: hop1 (lg fp32->h, g fp32->fp32, pmy) ; mode 1: hops 2-4 (lg h->h, g fp32->fp32)
__global__ void hops_kernel(
    const float* __restrict__ zf, const uint2* __restrict__ zh,
    const int* __restrict__ off_lg, const int* __restrict__ csr_lg, uint2* __restrict__ o_lg,
    const float* __restrict__ zg, const int* __restrict__ off_g, const int* __restrict__ csr_g,
    float* __restrict__ o_g,
    const float* __restrict__ y3, const int* __restrict__ eid3, float* __restrict__ o3, int n3,
    int mode)
{
    long long t = (long long)blockIdx.x * blockDim.x + threadIdx.x;
    int r = (int)(t >> 3);
    int lane = (int)(t & 7);
    if (r < NE) {
        if (mode == 0) pull_f32_h(zf, off_lg, csr_lg, o_lg, r, lane);
        else           pull_h_h(zh, off_lg, csr_lg, o_lg, r, lane);
    } else if (r < NE + NN) {
        pull_f32_f32(zg, off_g, csr_g, o_g, r - NE, lane);
    } else if (r < NE + NN + n3) {
        pull_f32_f32(y3, off_g, eid3, o3, r - NE - NN, lane);
    }
}

// ================= fused assemble (f32x2) =================
__device__ __forceinline__ void mv_acc2(u64 acc[16], const float* __restrict__ vec,
                                        float scale, const u64 (&W)[F][16], bool streaming) {
#pragma unroll 1
    for (int k4 = 0; k4 < 8; k4++) {
        float4 v = streaming ? __ldcs((const float4*)vec + k4) : *((const float4*)vec + k4);
        float c0 = v.x * scale, c1 = v.y * scale, c2 = v.z * scale, c3 = v.w * scale;
        u64 a0 = pack2(c0, c0), a1 = pack2(c1, c1), a2 = pack2(c2, c2), a3 = pack2(c3, c3);
#pragma unroll
        for (int j = 0; j < 16; j++) acc[j] = fma2(a0, W[k4 * 4 + 0][j], acc[j]);
#pragma unroll
        for (int j = 0; j < 16; j++) acc[j] = fma2(a1, W[k4 * 4 + 1][j], acc[j]);
#pragma unroll
        for (int j = 0; j < 16; j++) acc[j] = fma2(a2, W[k4 * 4 + 2][j], acc[j]);
#pragma unroll
        for (int j = 0; j < 16; j++) acc[j] = fma2(a3, W[k4 * 4 + 3][j], acc[j]);
    }
}

__device__ __forceinline__ void mv_acc2_h(u64 acc[16], const uint2* __restrict__ vec,
                                          const u64 (&W)[F][16]) {
#pragma unroll 1
    for (int k4 = 0; k4 < 8; k4++) {
        uint2 u = __ldcs(vec + k4);
        __half2 h0 = *(__half2*)&u.x;
        __half2 h1 = *(__half2*)&u.y;
        float2 f0 = __half22float2(h0);
        float2 f1 = __half22float2(h1);
        u64 a0 = pack2(f0.x, f0.x), a1 = pack2(f0.y, f0.y);
        u64 a2 = pack2(f1.x, f1.x), a3 = pack2(f1.y, f1.y);
#pragma unroll
        for (int j = 0; j < 16; j++) acc[j] = fma2(a0, W[k4 * 4 + 0][j], acc[j]);
#pragma unroll
        for (int j = 0; j < 16; j++) acc[j] = fma2(a1, W[k4 * 4 + 1][j], acc[j]);
#pragma unroll
        for (int j = 0; j < 16; j++) acc[j] = fma2(a2, W[k4 * 4 + 2][j], acc[j]);
#pragma unroll
        for (int j = 0; j < 16; j++) acc[j] = fma2(a3, W[k4 * 4 + 3][j], acc[j]);
    }
}

__global__ void assemble_both_kernel(
    const float* __restrict__ xb, const float* __restrict__ xdeg, const float* __restrict__ xextra,
    const float* __restrict__ xz0, const float* __restrict__ xz1, const float* __restrict__ xz2,
    const float* __restrict__ xWm, const float* __restrict__ xbm,
    const float* __restrict__ xWl, const float* __restrict__ xbl,
    float* __restrict__ xout, int nx, int bx,
    const float* __restrict__ yb, const float* __restrict__ ydeg, const float* __restrict__ yextra,
    const int* __restrict__ gatherIdx,
    const uint2* __restrict__ yz0, const uint2* __restrict__ yz1, const uint2* __restrict__ yz2,
    const float* __restrict__ yWm, const float* __restrict__ ybm,
    const float* __restrict__ yWl, const float* __restrict__ ybl,
    float* __restrict__ yout, int ny)
{
    bool isX = (int)blockIdx.x < bx;
    const float* Wmain = isX ? xWm : yWm;
    const float* bmain = isX ? xbm : ybm;
    const float* Wlist = isX ? xWl : yWl;
    const float* blist = isX ? xbl : ybl;

    __shared__ u64 sW[6][F][16];
    __shared__ u64 sb[16];
    for (int i = threadIdx.x; i < 6 * F * 16; i += blockDim.x) {
        int m = i >> 9;
        int rem = i & 511;
        int k = rem >> 4;
        int j2 = rem & 15;
        const float* W = (m < 3) ? (Wmain + m * 1024) : (Wlist + (m - 3) * 1024);
        sW[m][k][j2] = pack2(W[(2 * j2) * 32 + k], W[(2 * j2 + 1) * 32 + k]);
    }
    if (threadIdx.x < 16) {
        int j2 = threadIdx.x;
        float b0 = 0.f, b1 = 0.f;
#pragma unroll
        for (int m = 0; m < 3; m++) {
            b0 += bmain[m * 32 + 2 * j2] + blist[m * 32 + 2 * j2];
            b1 += bmain[m * 32 + 2 * j2 + 1] + blist[m * 32 + 2 * j2 + 1];
        }
        sb[j2] = pack2(b0, b1);
    }
    __syncthreads();

    u64 acc[16];
#pragma unroll
    for (int j = 0; j < 16; j++) acc[j] = sb[j];

    float* out;
    int r;
    if (isX) {
        r = (int)blockIdx.x * blockDim.x + threadIdx.x;
        if (r >= nx) return;
        out = xout;
        size_t r32 = (size_t)r * F;
        float dg = xdeg[r];
        mv_acc2(acc, xb + r32, 1.f, sW[0], false);
        mv_acc2(acc, xb + r32, dg,  sW[1], false);
        mv_acc2(acc, xextra + r32, 1.f, sW[2], true);
        mv_acc2(acc, xz0 + r32, 1.f, sW[3], true);
        mv_acc2(acc, xz1 + r32, 1.f, sW[4], true);
        mv_acc2(acc, xz2 + r32, 1.f, sW[5], true);
    } else {
        r = ((int)blockIdx.x - bx) * blockDim.x + threadIdx.x;
        if (r >= ny) return;
        out = yout;
        size_t r32 = (size_t)r * F;
        float dg = ydeg[r];
        mv_acc2(acc, yb + r32, 1.f, sW[0], false);
        mv_acc2(acc, yb + r32, dg,  sW[1], false);
        mv_acc2(acc, yextra + (size_t)__ldg(gatherIdx + r) * F, 1.f, sW[2], false);
        mv_acc2_h(acc, yz0 + (size_t)r * 8, sW[3]);
        mv_acc2_h(acc, yz1 + (size_t)r * 8, sW[4]);
        mv_acc2_h(acc, yz2 + (size_t)r * 8, sW[5]);
    }

    float vals[F];
#pragma unroll
    for (int j = 0; j < 16; j++) unpack2(acc[j], vals[2 * j], vals[2 * j + 1]);
#pragma unroll
    for (int j = F / 2; j < F; j++) vals[j] = fmaxf(vals[j], 0.f);

    float4* op = (float4*)(out + (size_t)r * F);
#pragma unroll
    for (int j = 0; j < 8; j++)
        op[j] = make_float4(vals[4 * j], vals[4 * j + 1], vals[4 * j + 2], vals[4 * j + 3]);
}

// ================= BN stats =================
__global__ void stats_both_kernel(const float* __restrict__ vx, const float* __restrict__ vy,
                                  int gx, float* __restrict__ st) {
    bool isX = (int)blockIdx.x < gx;
    const float* v = isX ? vx : vy;
    long long nRows = isX ? NN : NE;
    float* s0 = st + (isX ? 0 : 64);
    int nb = isX ? gx : (gridDim.x - gx);
    int rb = isX ? (int)blockIdx.x : (int)blockIdx.x - gx;

    int col = threadIdx.x & 31;
    int w = threadIdx.x >> 5;
    int warpsPerBlock = blockDim.x >> 5;
    float s = 0.f, s2 = 0.f;
    for (long long r = (long long)rb * warpsPerBlock + w; r < nRows;
         r += (long long)nb * warpsPerBlock) {
        float val = v[r * F + col];
        s += val;
        s2 += val * val;
    }
    __shared__ float sm[2][8][F];
    sm[0][w][col] = s;
    sm[1][w][col] = s2;
    __syncthreads();
    if (threadIdx.x < F) {
        float a = 0.f, b = 0.f;
#pragma unroll
        for (int ww = 0; ww < 8; ww++) { a += sm[0][ww][threadIdx.x]; b += sm[1][ww][threadIdx.x]; }
        atomicAdd(&s0[threadIdx.x], a);
        atomicAdd(&s0[F + threadIdx.x], b);
    }
}

// ================= BN normalize =================
__global__ void normalize_both_kernel(float* __restrict__ vx, float* __restrict__ vy,
                                      int gx, const float* __restrict__ st,
                                      const float* __restrict__ sx, const float* __restrict__ bxx,
                                      const float* __restrict__ sy, const float* __restrict__ byy) {
    bool isX = (int)blockIdx.x < gx;
    float* v = isX ? vx : vy;
    long long nRows = isX ? NN : NE;
    const float* s0 = st + (isX ? 0 : 64);
    const float* scale = isX ? sx : sy;
    const float* bias  = isX ? bxx : byy;
    int nb = isX ? gx : (gridDim.x - gx);
    int rb = isX ? (int)blockIdx.x : (int)blockIdx.x - gx;

    __shared__ float mulc[F], addc[F];
    if (threadIdx.x < F) {
        float m = s0[threadIdx.x] / (float)nRows;
        float var = s0[F + threadIdx.x] / (float)nRows - m * m;
        float g = rsqrtf(var + 1e-5f) * scale[threadIdx.x];
        mulc[threadIdx.x] = g;
        addc[threadIdx.x] = bias[threadIdx.x] - m * g;
    }
    __syncthreads();
    int col = threadIdx.x & 31;
    int w = threadIdx.x >> 5;
    int warpsPerBlock = blockDim.x >> 5;
    for (long long r = (long long)rb * warpsPerBlock + w; r < nRows;
         r += (long long)nb * warpsPerBlock) {
        v[r * F + col] = fmaf(v[r * F + col], mulc[col], addc[col]);
    }
}

// ================= launcher =================
extern "C" void kernel_launch(void* const* d_in, const int* in_sizes, int n_in,
                              void* d_out, int out_size) {
    const float* x            = (const float*)d_in[0];
    const float* y            = (const float*)d_in[1];
    const float* deg_g        = (const float*)d_in[2];
    const float* deg_lg       = (const float*)d_in[3];
    const float* theta_main_w = (const float*)d_in[4];
    const float* theta_main_b = (const float*)d_in[5];
    const float* theta_list_w = (const float*)d_in[6];
    const float* theta_list_b = (const float*)d_in[7];
    const float* gamma_main_w = (const float*)d_in[8];
    const float* gamma_main_b = (const float*)d_in[9];
    const float* gamma_list_w = (const float*)d_in[10];
    const float* gamma_list_b = (const float*)d_in[11];
    const float* bn_x_scale   = (const float*)d_in[12];
    const float* bn_x_bias    = (const float*)d_in[13];
    const float* bn_y_scale   = (const float*)d_in[14];
    const float* bn_y_bias    = (const float*)d_in[15];
    const int*   g_src        = (const int*)d_in[16];
    const int*   g_dst        = (const int*)d_in[17];
    const int*   lg_src       = (const int*)d_in[18];
    const int*   lg_dst       = (const int*)d_in[19];
    const int*   pm_pd        = (const int*)d_in[20];

    float* out_x = (float*)d_out;
    float* out_y = (float*)d_out + (size_t)NN * F;

    float *zg0, *zg1, *zg2, *zgt, *pmy, *st;
    uint2 *zl0, *zl1, *zl2, *zlt;
    int *cnt, *incl, *off, *rank, *csr_src_g, *csr_eid_g, *csr_lg, *bsum;
    cudaGetSymbolAddress((void**)&zg0, d_zg0);
    cudaGetSymbolAddress((void**)&zg1, d_zg1);
    cudaGetSymbolAddress((void**)&zg2, d_zg2);
    cudaGetSymbolAddress((void**)&zgt, d_zgt);
    cudaGetSymbolAddress((void**)&pmy, d_pmy);
    cudaGetSymbolAddress((void**)&zl0, d_zl0);
    cudaGetSymbolAddress((void**)&zl1, d_zl1);
    cudaGetSymbolAddress((void**)&zl2, d_zl2);
    cudaGetSymbolAddress((void**)&zlt, d_zlt);
    cudaGetSymbolAddress((void**)&st,  d_stats);
    cudaGetSymbolAddress((void**)&cnt, d_cnt);
    cudaGetSymbolAddress((void**)&incl, d_incl);
    cudaGetSymbolAddress((void**)&off, d_off);
    cudaGetSymbolAddress((void**)&rank, d_rank);
    cudaGetSymbolAddress((void**)&csr_src_g, d_csr_src_g);
    cudaGetSymbolAddress((void**)&csr_eid_g, d_csr_eid_g);
    cudaGetSymbolAddress((void**)&csr_lg, d_csr_lg);
    cudaGetSymbolAddress((void**)&bsum, d_bsum);

    int* off_g  = off;
    int* off_lg = off + NN + 1;

    const int TB = 256;
    int eBlocks = (NE + NLE + TB - 1) / TB;

    // ===== CSR build =====
    hist_both_kernel<<<eBlocks, TB>>>(g_dst, lg_dst, cnt, rank, st);
    scan_block_kernel<<<SBG + SBL, SCAN_B>>>(cnt, incl, bsum);
    scan_add_kernel<<<SBG + SBL, SCAN_B>>>(incl, cnt, bsum, off);
    fill_both_kernel<<<eBlocks, TB>>>(g_src, g_dst, lg_src, lg_dst,
                                      off_g, off_lg, rank,
                                      csr_src_g, csr_eid_g, csr_lg);

    // ===== hops =====
    long long rows1 = (long long)(NE + NN + NN) * 8;
    long long rows  = (long long)(NE + NN) * 8;
    int hBlocks1 = (int)((rows1 + TB - 1) / TB);
    int hBlocks  = (int)((rows + TB - 1) / TB);

    // hop1: lg y(f32)->zl0(h), g x->zg0, pmy = segsum(y by eid)
    hops_kernel<<<hBlocks1, TB>>>(y, nullptr, off_lg, csr_lg, zl0,
                                  x, off_g, csr_src_g, zg0,
                                  y, csr_eid_g, pmy, NN, 0);
    hops_kernel<<<hBlocks, TB>>>(nullptr, zl0, off_lg, csr_lg, zl1,
                                 zg0, off_g, csr_src_g, zg1,
                                 nullptr, nullptr, nullptr, 0, 1);
    hops_kernel<<<hBlocks, TB>>>(nullptr, zl1, off_lg, csr_lg, zlt,
                                 zg1, off_g, csr_src_g, zgt,
                                 nullptr, nullptr, nullptr, 0, 1);
    hops_kernel<<<hBlocks, TB>>>(nullptr, zlt, off_lg, csr_lg, zl2,
                                 zgt, off_g, csr_src_g, zg2,
                                 nullptr, nullptr, nullptr, 0, 1);

    // ===== assemble =====
    int bx = (NN + TB - 1) / TB;
    int by = (NE + TB - 1) / TB;
    assemble_both_kernel<<<bx + by, TB>>>(
        x, deg_g, pmy, zg0, zg1, zg2,
        theta_main_w, theta_main_b, theta_list_w, theta_list_b, out_x, NN, bx,
        y, deg_lg, x, pm_pd, zl0, zl1, zl2,
        gamma_main_w, gamma_main_b, gamma_list_w, gamma_list_b, out_y, NE);

    // ===== batchnorm =====
    stats_both_kernel<<<512 + 2048, TB>>>(out_x, out_y, 512, st);
    normalize_both_kernel<<<512 + 2048, TB>>>(out_x, out_y, 512, st,
                                              bn_x_scale, bn_x_bias, bn_y_scale, bn_y_bias);
}